// round 4
// baseline (speedup 1.0000x reference)
#include <cuda_runtime.h>
#include <stdint.h>

// Fixed problem shapes
#define BQ 2
#define NQ 16384
#define SQ 4096
#define CQ 64
#define NS 32
#define OUTC 67
#define NCELL 1000            // 10x10x10 grid, cell = radius = 0.1
#define WARPS_B 8             // centers per fused-kernel block

// Device scratch (no allocations allowed)
__device__ float4 g_xyzp[BQ * NQ];                  // packed xyz (orig order)
__device__ float4 g_sorted[BQ * NQ];                // cell-sorted xyz, .w = orig idx bits
__device__ float  g_featT[(size_t)BQ * NQ * CQ];    // features [B,N,C]
__device__ int    g_cellstart[BQ * (NCELL + 1)];    // exclusive prefix, [1000] = N

__device__ __forceinline__ int cell_of(float v) {
    int c = (int)(v * 10.0f);
    return min(9, max(0, c));
}

// ---------------------------------------------------------------------------
// K1 prep: blocks 0..1 = full counting sort (one block per batch),
//          blocks 2..  = feature transpose [B,C,N] -> [B,N,C].
// All stateless: no global counters carried between replays.
// ---------------------------------------------------------------------------
__global__ __launch_bounds__(256)
void prep_kernel(const float* __restrict__ xyz,
                 const float* __restrict__ feat) {
    if (blockIdx.x < BQ) {
        // ---------------- binning block: one batch ----------------
        __shared__ int hist[NCELL];
        __shared__ int cursor[NCELL];
        __shared__ int partial[256];

        const int b = blockIdx.x;
        const int t = threadIdx.x;

        for (int i = t; i < NCELL; i += 256) hist[i] = 0;
        __syncthreads();

        // pack + histogram (thread t owns points t, t+256, ...)
        const float* xb = xyz + (size_t)b * NQ * 3;
        for (int i = t; i < NQ; i += 256) {
            float x = xb[3 * i + 0], y = xb[3 * i + 1], z = xb[3 * i + 2];
            g_xyzp[b * NQ + i] = make_float4(x, y, z, 0.0f);
            int cell = (cell_of(z) * 10 + cell_of(y)) * 10 + cell_of(x);
            atomicAdd(&hist[cell], 1);
        }
        __syncthreads();

        // scan: thread t (<250) sums bins 4t..4t+3, block-scan partials
        int own = 0;
        if (t < 250) {
#pragma unroll
            for (int j = 0; j < 4; j++) own += hist[4 * t + j];
        }
        partial[t] = own;
        __syncthreads();
#pragma unroll
        for (int d = 1; d < 256; d <<= 1) {
            int v = (t >= d) ? partial[t - d] : 0;
            __syncthreads();
            partial[t] += v;
            __syncthreads();
        }
        if (t < 250) {
            int run = partial[t] - own;             // exclusive base
#pragma unroll
            for (int j = 0; j < 4; j++) {
                int bin = 4 * t + j;
                int c = hist[bin];
                g_cellstart[b * (NCELL + 1) + bin] = run;
                cursor[bin] = run;
                run += c;
            }
        }
        if (t == 0) g_cellstart[b * (NCELL + 1) + NCELL] = NQ;
        __syncthreads();

        // scatter (re-read own writes: same thread, program order)
        for (int i = t; i < NQ; i += 256) {
            float4 p = g_xyzp[b * NQ + i];
            int cell = (cell_of(p.z) * 10 + cell_of(p.y)) * 10 + cell_of(p.x);
            int pos = atomicAdd(&cursor[cell], 1);
            g_sorted[b * NQ + pos] = make_float4(p.x, p.y, p.z, __int_as_float(i));
        }
    } else {
        // ---------------- transpose block ----------------
        __shared__ float tile[32][33];
        int id = blockIdx.x - BQ;
        int n0 = (id & 511) * 32;                   // 512 n-tiles
        int c0 = ((id >> 9) & 1) * 32;              // 2 c-tiles
        int b  = id >> 10;                          // 2 batches
        int tx = threadIdx.x & 31;
        int ty = threadIdx.x >> 5;                  // 0..7

#pragma unroll
        for (int j = 0; j < 32; j += 8)
            tile[ty + j][tx] = feat[((size_t)b * CQ + (c0 + ty + j)) * NQ + (n0 + tx)];
        __syncthreads();
#pragma unroll
        for (int j = 0; j < 32; j += 8)
            g_featT[((size_t)b * NQ + (n0 + ty + j)) * CQ + (c0 + tx)] = tile[tx][ty + j];
    }
}

// ---------------------------------------------------------------------------
// K2 fused: ball query (grid + bitmask) then grouping, one warp per center.
// ---------------------------------------------------------------------------
__global__ __launch_bounds__(WARPS_B * 32)
void query_group_kernel(const float* __restrict__ new_xyz,
                        float* __restrict__ out) {
    __shared__ unsigned mask[WARPS_B][NQ / 32];     // 2 KB per warp
    __shared__ int      sh_idx[WARPS_B][NS];

    const int warp = threadIdx.x >> 5;
    const int lane = threadIdx.x & 31;
    const int center = blockIdx.x * WARPS_B + warp;
    const int b = center / SQ;
    const int s = center % SQ;

    const float cx = new_xyz[3 * center + 0];
    const float cy = new_xyz[3 * center + 1];
    const float cz = new_xyz[3 * center + 2];
    const float r2 = (float)(0.1 * 0.1);

#pragma unroll
    for (int i = lane; i < NQ / 32; i += 32) mask[warp][i] = 0;
    __syncwarp();

    // neighbor cell ranges with guard band against boundary rounding
    const int x0 = max(0, (int)floorf((cx - 0.1f) * 10.0f - 0.002f));
    const int x1 = min(9, (int)floorf((cx + 0.1f) * 10.0f + 0.002f));
    const int y0 = max(0, (int)floorf((cy - 0.1f) * 10.0f - 0.002f));
    const int y1 = min(9, (int)floorf((cy + 0.1f) * 10.0f + 0.002f));
    const int z0 = max(0, (int)floorf((cz - 0.1f) * 10.0f - 0.002f));
    const int z1 = min(9, (int)floorf((cz + 0.1f) * 10.0f + 0.002f));

    const float4* __restrict__ srt = g_sorted + (size_t)b * NQ;
    const int* __restrict__ cs = g_cellstart + b * (NCELL + 1);

    for (int zc = z0; zc <= z1; zc++) {
        for (int yc = y0; yc <= y1; yc++) {
            int rowbase = (zc * 10 + yc) * 10;
            int st = cs[rowbase + x0];
            int en = cs[rowbase + x1 + 1];          // x-contiguous cells
            for (int ibase = st; ibase < en; ibase += 32) {
                int i = ibase + lane;
                if (i < en) {
                    float4 p = srt[i];
                    float dx = __fadd_rn(cx, -p.x);
                    float dy = __fadd_rn(cy, -p.y);
                    float dz = __fadd_rn(cz, -p.z);
                    float d2 = __fadd_rn(__fadd_rn(__fmul_rn(dx, dx), __fmul_rn(dy, dy)),
                                         __fmul_rn(dz, dz));
                    if (d2 < r2) {
                        int oi = __float_as_int(p.w);
                        atomicOr(&mask[warp][oi >> 5], 1u << (oi & 31));
                    }
                }
            }
        }
    }
    __syncwarp();

    // extract first NS set bits in ascending original-index order
    int cnt = 0;
    for (int w0 = 0; w0 < NQ / 32 && cnt < NS; w0 += 32) {
        unsigned word = mask[warp][w0 + lane];
        int pc = __popc(word);
        int pre = pc;
#pragma unroll
        for (int d = 1; d < 32; d <<= 1) {
            int tval = __shfl_up_sync(0xffffffffu, pre, d);
            if (lane >= d) pre += tval;
        }
        int tot = __shfl_sync(0xffffffffu, pre, 31);
        int pos = cnt + pre - pc;
        if (word && pos < NS) {
            unsigned w = word;
            while (w && pos < NS) {
                int bpos = __ffs(w) - 1;
                sh_idx[warp][pos] = (w0 + lane) * 32 + bpos;
                w &= w - 1;
                pos++;
            }
        }
        cnt += tot;
    }
    __syncwarp();

    // lane k owns sample k; pad with first hit, 0 if none
    int myidx = (cnt == 0) ? 0 : sh_idx[warp][(lane < cnt) ? lane : 0];

    // grouped_xyz channels 0..2 (coalesced over lane=k)
    float4 p = g_xyzp[(size_t)b * NQ + myidx];
    const size_t chan_stride = (size_t)SQ * NS;
    float* ob = out + ((size_t)b * OUTC * SQ + s) * NS + lane;
    ob[0 * chan_stride] = __fadd_rn(p.x, -cx);
    ob[1 * chan_stride] = __fadd_rn(p.y, -cy);
    ob[2 * chan_stride] = __fadd_rn(p.z, -cz);

    // feature channels 3..66: lane loads its own row as float4 chunks;
    // chunk cc / cc+1 share a 32B sector -> odd iterations hit L1.
    const float4* __restrict__ ft4 =
        (const float4*)(g_featT + (size_t)b * NQ * CQ);
    const float4* myrow = ft4 + (size_t)myidx * 16;
    float* oc = ob + 3 * chan_stride;
#pragma unroll
    for (int cc = 0; cc < 16; cc++) {
        float4 v = myrow[cc];
        float* o = oc + (size_t)(4 * cc) * chan_stride;
        __stcs(o + 0 * chan_stride, v.x);           // streaming: don't evict featT
        __stcs(o + 1 * chan_stride, v.y);
        __stcs(o + 2 * chan_stride, v.z);
        __stcs(o + 3 * chan_stride, v.w);
    }
}

// ---------------------------------------------------------------------------
// Launch
// ---------------------------------------------------------------------------
extern "C" void kernel_launch(void* const* d_in, const int* in_sizes, int n_in,
                              void* d_out, int out_size) {
    const float* xyz     = (const float*)d_in[0];   // [B,N,3]
    const float* new_xyz = (const float*)d_in[1];   // [B,S,3]
    const float* feat    = (const float*)d_in[2];   // [B,C,N]
    float* out = (float*)d_out;                     // [B,67,S,NS]

    // K1: binning blocks (0..1) + transpose blocks (2..2049) in one launch
    prep_kernel<<<BQ + BQ * (CQ / 32) * (NQ / 32), 256>>>(xyz, feat);

    // K2: fused ball query + grouping
    query_group_kernel<<<(BQ * SQ) / WARPS_B, WARPS_B * 32>>>(new_xyz, out);
}

// round 5
// speedup vs baseline: 1.1023x; 1.1023x over previous
#include <cuda_runtime.h>
#include <stdint.h>

// Fixed problem shapes
#define BQ 2
#define NQ 16384
#define SQ 4096
#define CQ 64
#define NS 32
#define OUTC 67
#define NCELL 1000            // 10x10x10 grid, cell = radius = 0.1
#define WARPS_B 8             // centers per ball-query block

// Device scratch (no allocations allowed)
__device__ float4 g_xyzp[BQ * NQ];                  // packed xyz (orig order)
__device__ float4 g_sorted[BQ * NQ];                // cell-sorted xyz, .w = orig idx bits
__device__ float  g_featT[(size_t)BQ * NQ * CQ];    // features [B,N,C]
__device__ int    g_idx[BQ * SQ * NS];              // final sample indices
__device__ int    g_cellstart[BQ * (NCELL + 1)];    // exclusive prefix, [1000] = N

__device__ __forceinline__ int cell_of(float v) {
    int c = (int)(v * 10.0f);
    return min(9, max(0, c));
}

// ---------------------------------------------------------------------------
// K1 prep: blocks 0..1 = full counting sort (one block per batch),
//          blocks 2..  = feature transpose [B,C,N] -> [B,N,C].
// Stateless across replays (no persistent global counters).
// ---------------------------------------------------------------------------
__global__ __launch_bounds__(256)
void prep_kernel(const float* __restrict__ xyz,
                 const float* __restrict__ feat) {
    if (blockIdx.x < BQ) {
        // ---------------- binning block: one batch ----------------
        __shared__ int hist[NCELL];
        __shared__ int cursor[NCELL];
        __shared__ int partial[256];

        const int b = blockIdx.x;
        const int t = threadIdx.x;

        for (int i = t; i < NCELL; i += 256) hist[i] = 0;
        __syncthreads();

        const float* xb = xyz + (size_t)b * NQ * 3;
        for (int i = t; i < NQ; i += 256) {
            float x = xb[3 * i + 0], y = xb[3 * i + 1], z = xb[3 * i + 2];
            g_xyzp[b * NQ + i] = make_float4(x, y, z, 0.0f);
            int cell = (cell_of(z) * 10 + cell_of(y)) * 10 + cell_of(x);
            atomicAdd(&hist[cell], 1);
        }
        __syncthreads();

        // scan: thread t (<250) sums bins 4t..4t+3; block-scan the partials
        int own = 0;
        if (t < 250) {
#pragma unroll
            for (int j = 0; j < 4; j++) own += hist[4 * t + j];
        }
        partial[t] = own;
        __syncthreads();
#pragma unroll
        for (int d = 1; d < 256; d <<= 1) {
            int v = (t >= d) ? partial[t - d] : 0;
            __syncthreads();
            partial[t] += v;
            __syncthreads();
        }
        if (t < 250) {
            int run = partial[t] - own;             // exclusive base
#pragma unroll
            for (int j = 0; j < 4; j++) {
                int bin = 4 * t + j;
                int c = hist[bin];
                g_cellstart[b * (NCELL + 1) + bin] = run;
                cursor[bin] = run;
                run += c;
            }
        }
        if (t == 0) g_cellstart[b * (NCELL + 1) + NCELL] = NQ;
        __syncthreads();

        // scatter (each thread re-reads its own earlier global writes)
        for (int i = t; i < NQ; i += 256) {
            float4 p = g_xyzp[b * NQ + i];
            int cell = (cell_of(p.z) * 10 + cell_of(p.y)) * 10 + cell_of(p.x);
            int pos = atomicAdd(&cursor[cell], 1);
            g_sorted[b * NQ + pos] = make_float4(p.x, p.y, p.z, __int_as_float(i));
        }
    } else {
        // ---------------- transpose block ----------------
        __shared__ float tile[32][33];
        int id = blockIdx.x - BQ;
        int n0 = (id & 511) * 32;                   // 512 n-tiles
        int c0 = ((id >> 9) & 1) * 32;              // 2 c-tiles
        int b  = id >> 10;                          // 2 batches
        int tx = threadIdx.x & 31;
        int ty = threadIdx.x >> 5;                  // 0..7

#pragma unroll
        for (int j = 0; j < 32; j += 8)
            tile[ty + j][tx] = feat[((size_t)b * CQ + (c0 + ty + j)) * NQ + (n0 + tx)];
        __syncthreads();
#pragma unroll
        for (int j = 0; j < 32; j += 8)
            g_featT[((size_t)b * NQ + (n0 + ty + j)) * CQ + (c0 + tx)] = tile[tx][ty + j];
    }
}

// ---------------------------------------------------------------------------
// K2: ball query via grid + per-warp bitmask; writes g_idx and xyz channels.
// ---------------------------------------------------------------------------
__global__ __launch_bounds__(WARPS_B * 32)
void ball_query_grid_kernel(const float* __restrict__ new_xyz,
                            float* __restrict__ out) {
    __shared__ unsigned mask[WARPS_B][NQ / 32];     // 2 KB per warp
    __shared__ int      sh_idx[WARPS_B][NS];

    const int warp = threadIdx.x >> 5;
    const int lane = threadIdx.x & 31;
    const int center = blockIdx.x * WARPS_B + warp;
    const int b = center / SQ;
    const int s = center % SQ;

    const float cx = new_xyz[3 * center + 0];
    const float cy = new_xyz[3 * center + 1];
    const float cz = new_xyz[3 * center + 2];
    const float r2 = (float)(0.1 * 0.1);

#pragma unroll
    for (int i = lane; i < NQ / 32; i += 32) mask[warp][i] = 0;
    __syncwarp();

    // neighbor cell ranges with guard band against boundary rounding
    const int x0 = max(0, (int)floorf((cx - 0.1f) * 10.0f - 0.002f));
    const int x1 = min(9, (int)floorf((cx + 0.1f) * 10.0f + 0.002f));
    const int y0 = max(0, (int)floorf((cy - 0.1f) * 10.0f - 0.002f));
    const int y1 = min(9, (int)floorf((cy + 0.1f) * 10.0f + 0.002f));
    const int z0 = max(0, (int)floorf((cz - 0.1f) * 10.0f - 0.002f));
    const int z1 = min(9, (int)floorf((cz + 0.1f) * 10.0f + 0.002f));

    const float4* __restrict__ srt = g_sorted + (size_t)b * NQ;
    const int* __restrict__ cs = g_cellstart + b * (NCELL + 1);

    for (int zc = z0; zc <= z1; zc++) {
        for (int yc = y0; yc <= y1; yc++) {
            int rowbase = (zc * 10 + yc) * 10;
            int st = cs[rowbase + x0];
            int en = cs[rowbase + x1 + 1];          // x-contiguous cells
            for (int ibase = st; ibase < en; ibase += 32) {
                int i = ibase + lane;
                if (i < en) {
                    float4 p = srt[i];
                    float dx = __fadd_rn(cx, -p.x);
                    float dy = __fadd_rn(cy, -p.y);
                    float dz = __fadd_rn(cz, -p.z);
                    float d2 = __fadd_rn(__fadd_rn(__fmul_rn(dx, dx), __fmul_rn(dy, dy)),
                                         __fmul_rn(dz, dz));
                    if (d2 < r2) {
                        int oi = __float_as_int(p.w);
                        atomicOr(&mask[warp][oi >> 5], 1u << (oi & 31));
                    }
                }
            }
        }
    }
    __syncwarp();

    // extract first NS set bits in ascending original-index order
    int cnt = 0;
    for (int w0 = 0; w0 < NQ / 32 && cnt < NS; w0 += 32) {
        unsigned word = mask[warp][w0 + lane];
        int pc = __popc(word);
        int pre = pc;
#pragma unroll
        for (int d = 1; d < 32; d <<= 1) {
            int tval = __shfl_up_sync(0xffffffffu, pre, d);
            if (lane >= d) pre += tval;
        }
        int tot = __shfl_sync(0xffffffffu, pre, 31);
        int pos = cnt + pre - pc;
        if (word && pos < NS) {
            unsigned w = word;
            while (w && pos < NS) {
                int bpos = __ffs(w) - 1;
                sh_idx[warp][pos] = (w0 + lane) * 32 + bpos;
                w &= w - 1;
                pos++;
            }
        }
        cnt += tot;
    }
    __syncwarp();

    int myidx = (cnt == 0) ? 0 : sh_idx[warp][(lane < cnt) ? lane : 0];
    g_idx[center * NS + lane] = myidx;

    // grouped_xyz channels 0..2 (coalesced over lane=k)
    float4 p = g_xyzp[(size_t)b * NQ + myidx];
    const size_t chan_stride = (size_t)SQ * NS;
    float* ob = out + ((size_t)b * OUTC * SQ + s) * NS + lane;
    __stcs(ob + 0 * chan_stride, __fadd_rn(p.x, -cx));
    __stcs(ob + 1 * chan_stride, __fadd_rn(p.y, -cy));
    __stcs(ob + 2 * chan_stride, __fadd_rn(p.z, -cz));
}

// ---------------------------------------------------------------------------
// K3: feature grouping, one 128-thread block per center.
// Coalesced float4 row gather -> conflict-free smem transpose -> coalesced
// streaming stores over the sample dimension.
// ---------------------------------------------------------------------------
__global__ __launch_bounds__(128)
void group_feat_kernel(float* __restrict__ out) {
    __shared__ float4 sf4[NS][17];                  // pitch 17 float4 -> conflict-free
    __shared__ int    sidx[NS];

    const int center = blockIdx.x;
    const int b = center / SQ;
    const int s = center % SQ;
    const int tid = threadIdx.x;

    if (tid < NS) sidx[tid] = g_idx[center * NS + tid];
    __syncthreads();

    // gather: lanes 0..15 cover columns of one row (2 wavefronts/instr)
    const float4* __restrict__ ft4 =
        (const float4*)(g_featT + (size_t)b * NQ * CQ);
    const int r  = tid >> 4;       // 0..7
    const int c4 = tid & 15;       // 0..15
#pragma unroll
    for (int r0 = 0; r0 < NS; r0 += 8)
        sf4[r0 + r][c4] = __ldg(ft4 + (size_t)sidx[r0 + r] * 16 + c4);
    __syncthreads();

    // write: lane = sample k (coalesced 128B per store instruction)
    const int k = tid & 31;
    const int w = tid >> 5;        // 0..3
    const size_t chan_stride = (size_t)SQ * NS;
    float* ob = out + ((size_t)b * OUTC * SQ + s) * NS + k + 3 * chan_stride;
#pragma unroll
    for (int cc = w; cc < 16; cc += 4) {
        float4 v = sf4[k][cc];
        float* o = ob + (size_t)(4 * cc) * chan_stride;
        __stcs(o + 0 * chan_stride, v.x);
        __stcs(o + 1 * chan_stride, v.y);
        __stcs(o + 2 * chan_stride, v.z);
        __stcs(o + 3 * chan_stride, v.w);
    }
}

// ---------------------------------------------------------------------------
// Launch
// ---------------------------------------------------------------------------
extern "C" void kernel_launch(void* const* d_in, const int* in_sizes, int n_in,
                              void* d_out, int out_size) {
    const float* xyz     = (const float*)d_in[0];   // [B,N,3]
    const float* new_xyz = (const float*)d_in[1];   // [B,S,3]
    const float* feat    = (const float*)d_in[2];   // [B,C,N]
    float* out = (float*)d_out;                     // [B,67,S,NS]

    // K1: binning (blocks 0..1) + transpose (blocks 2..2049), one launch
    prep_kernel<<<BQ + BQ * (CQ / 32) * (NQ / 32), 256>>>(xyz, feat);

    // K2: ball query
    ball_query_grid_kernel<<<(BQ * SQ) / WARPS_B, WARPS_B * 32>>>(new_xyz, out);

    // K3: feature grouping
    group_feat_kernel<<<BQ * SQ, 128>>>(out);
}

// round 6
// speedup vs baseline: 1.5249x; 1.3835x over previous
#include <cuda_runtime.h>
#include <stdint.h>

// Fixed problem shapes
#define BQ 2
#define NQ 16384
#define SQ 4096
#define CQ 64
#define NS 32
#define OUTC 67
#define NCELL 1000            // 10x10x10 grid, cell = radius = 0.1
#define WARPS_B 8             // centers per ball-query block
#define HB 64                 // wide hist/scatter blocks
#define NTILE 2048            // total transpose tiles (512 n x 2 c x 2 b)

// Device scratch (no allocations allowed).
// g_cellcnt starts zero (static init) and is re-zeroed by the scan phase each
// replay, keeping the whole pipeline stateless under graph replay.
__device__ float4 g_xyzp[BQ * NQ];                  // packed xyz, cell id in .w
__device__ float4 g_sorted[BQ * NQ];                // cell-sorted xyz, orig idx in .w
__device__ float  g_featT[(size_t)BQ * NQ * CQ];    // features [B,N,C]
__device__ int    g_idx[BQ * SQ * NS];              // final sample indices
__device__ int    g_cellcnt[BQ * NCELL];            // histogram
__device__ int    g_cellstart[BQ * (NCELL + 1)];    // exclusive prefix, [1000] = N
__device__ int    g_cellfill[BQ * NCELL];           // scatter cursors

__device__ __forceinline__ int cell_of(float v) {
    int c = (int)(v * 10.0f);
    return min(9, max(0, c));
}

// one 32x32 transpose tile of [B,C,N] -> [B,N,C]; id in [0, NTILE)
__device__ __forceinline__ void transpose_tile(const float* __restrict__ feat, int id) {
    __shared__ float tile[32][33];
    int n0 = (id & 511) * 32;
    int c0 = ((id >> 9) & 1) * 32;
    int b  = id >> 10;
    int tx = threadIdx.x & 31;
    int ty = threadIdx.x >> 5;                      // 0..7

#pragma unroll
    for (int j = 0; j < 32; j += 8)
        tile[ty + j][tx] = feat[((size_t)b * CQ + (c0 + ty + j)) * NQ + (n0 + tx)];
    __syncthreads();
#pragma unroll
    for (int j = 0; j < 32; j += 8)
        g_featT[((size_t)b * NQ + (n0 + ty + j)) * CQ + (c0 + tx)] = tile[tx][ty + j];
}

// ---------------------------------------------------------------------------
// K1: blocks 0..HB-1 = pack + global-atomic histogram; rest = transpose tiles
// ---------------------------------------------------------------------------
__global__ __launch_bounds__(256)
void k1_hist(const float* __restrict__ xyz, const float* __restrict__ feat) {
    if (blockIdx.x < HB) {
        int i = blockIdx.x * (BQ * NQ / HB) + threadIdx.x;   // 512 pts per block
        int end = (blockIdx.x + 1) * (BQ * NQ / HB);
        for (; i < end; i += 256) {
            float x = xyz[3 * i + 0], y = xyz[3 * i + 1], z = xyz[3 * i + 2];
            int cell = (cell_of(z) * 10 + cell_of(y)) * 10 + cell_of(x);
            g_xyzp[i] = make_float4(x, y, z, __int_as_float(cell));
            int b = i >> 14;
            atomicAdd(&g_cellcnt[b * NCELL + cell], 1);
        }
    } else {
        transpose_tile(feat, blockIdx.x - HB);               // tiles 0..1023
    }
}

// ---------------------------------------------------------------------------
// K2: blocks 0..1 = per-batch scan over 1000 cells (re-zero counts);
//     rest = transpose tiles
// ---------------------------------------------------------------------------
__global__ __launch_bounds__(256)
void k2_scan(const float* __restrict__ feat) {
    if (blockIdx.x < BQ) {
        __shared__ int partial[256];
        const int b = blockIdx.x;
        const int t = threadIdx.x;

        int cnt4[4];
        int own = 0;
        if (t < 250) {
#pragma unroll
            for (int j = 0; j < 4; j++) {
                cnt4[j] = g_cellcnt[b * NCELL + 4 * t + j];
                own += cnt4[j];
            }
        }
        partial[t] = own;
        __syncthreads();
#pragma unroll
        for (int d = 1; d < 256; d <<= 1) {
            int v = (t >= d) ? partial[t - d] : 0;
            __syncthreads();
            partial[t] += v;
            __syncthreads();
        }
        if (t < 250) {
            int run = partial[t] - own;                      // exclusive base
#pragma unroll
            for (int j = 0; j < 4; j++) {
                int bin = 4 * t + j;
                g_cellstart[b * (NCELL + 1) + bin] = run;
                g_cellfill[b * NCELL + bin] = run;
                g_cellcnt[b * NCELL + bin] = 0;              // stateless for replay
                run += cnt4[j];
            }
        }
        if (t == 0) g_cellstart[b * (NCELL + 1) + NCELL] = NQ;
    } else {
        transpose_tile(feat, 1024 + blockIdx.x - BQ);        // tiles 1024..1535
    }
}

// ---------------------------------------------------------------------------
// K3: blocks 0..HB-1 = scatter into cell order; rest = transpose tiles
// ---------------------------------------------------------------------------
__global__ __launch_bounds__(256)
void k3_scatter(const float* __restrict__ feat) {
    if (blockIdx.x < HB) {
        int i = blockIdx.x * (BQ * NQ / HB) + threadIdx.x;
        int end = (blockIdx.x + 1) * (BQ * NQ / HB);
        for (; i < end; i += 256) {
            float4 p = g_xyzp[i];
            int cell = __float_as_int(p.w);
            int b = i >> 14, n = i & (NQ - 1);
            int pos = atomicAdd(&g_cellfill[b * NCELL + cell], 1);
            g_sorted[b * NQ + pos] = make_float4(p.x, p.y, p.z, __int_as_float(n));
        }
    } else {
        transpose_tile(feat, 1536 + blockIdx.x - HB);        // tiles 1536..2047
    }
}

// ---------------------------------------------------------------------------
// K4: ball query via grid + per-warp bitmask; writes g_idx and xyz channels
// ---------------------------------------------------------------------------
__global__ __launch_bounds__(WARPS_B * 32)
void ball_query_grid_kernel(const float* __restrict__ new_xyz,
                            float* __restrict__ out) {
    __shared__ unsigned mask[WARPS_B][NQ / 32];     // 2 KB per warp
    __shared__ int      sh_idx[WARPS_B][NS];

    const int warp = threadIdx.x >> 5;
    const int lane = threadIdx.x & 31;
    const int center = blockIdx.x * WARPS_B + warp;
    const int b = center / SQ;
    const int s = center % SQ;

    const float cx = new_xyz[3 * center + 0];
    const float cy = new_xyz[3 * center + 1];
    const float cz = new_xyz[3 * center + 2];
    const float r2 = (float)(0.1 * 0.1);

#pragma unroll
    for (int i = lane; i < NQ / 32; i += 32) mask[warp][i] = 0;
    __syncwarp();

    const int x0 = max(0, (int)floorf((cx - 0.1f) * 10.0f - 0.002f));
    const int x1 = min(9, (int)floorf((cx + 0.1f) * 10.0f + 0.002f));
    const int y0 = max(0, (int)floorf((cy - 0.1f) * 10.0f - 0.002f));
    const int y1 = min(9, (int)floorf((cy + 0.1f) * 10.0f + 0.002f));
    const int z0 = max(0, (int)floorf((cz - 0.1f) * 10.0f - 0.002f));
    const int z1 = min(9, (int)floorf((cz + 0.1f) * 10.0f + 0.002f));

    const float4* __restrict__ srt = g_sorted + (size_t)b * NQ;
    const int* __restrict__ cs = g_cellstart + b * (NCELL + 1);

    for (int zc = z0; zc <= z1; zc++) {
        for (int yc = y0; yc <= y1; yc++) {
            int rowbase = (zc * 10 + yc) * 10;
            int st = cs[rowbase + x0];
            int en = cs[rowbase + x1 + 1];          // x-contiguous cells
            for (int ibase = st; ibase < en; ibase += 32) {
                int i = ibase + lane;
                if (i < en) {
                    float4 p = srt[i];
                    float dx = __fadd_rn(cx, -p.x);
                    float dy = __fadd_rn(cy, -p.y);
                    float dz = __fadd_rn(cz, -p.z);
                    float d2 = __fadd_rn(__fadd_rn(__fmul_rn(dx, dx), __fmul_rn(dy, dy)),
                                         __fmul_rn(dz, dz));
                    if (d2 < r2) {
                        int oi = __float_as_int(p.w);
                        atomicOr(&mask[warp][oi >> 5], 1u << (oi & 31));
                    }
                }
            }
        }
    }
    __syncwarp();

    // extract first NS set bits in ascending original-index order
    int cnt = 0;
    for (int w0 = 0; w0 < NQ / 32 && cnt < NS; w0 += 32) {
        unsigned word = mask[warp][w0 + lane];
        int pc = __popc(word);
        int pre = pc;
#pragma unroll
        for (int d = 1; d < 32; d <<= 1) {
            int tval = __shfl_up_sync(0xffffffffu, pre, d);
            if (lane >= d) pre += tval;
        }
        int tot = __shfl_sync(0xffffffffu, pre, 31);
        int pos = cnt + pre - pc;
        if (word && pos < NS) {
            unsigned w = word;
            while (w && pos < NS) {
                int bpos = __ffs(w) - 1;
                sh_idx[warp][pos] = (w0 + lane) * 32 + bpos;
                w &= w - 1;
                pos++;
            }
        }
        cnt += tot;
    }
    __syncwarp();

    int myidx = (cnt == 0) ? 0 : sh_idx[warp][(lane < cnt) ? lane : 0];
    g_idx[center * NS + lane] = myidx;

    // grouped_xyz channels 0..2 (coalesced over lane=k)
    float4 p = g_xyzp[(size_t)b * NQ + myidx];
    const size_t chan_stride = (size_t)SQ * NS;
    float* ob = out + ((size_t)b * OUTC * SQ + s) * NS + lane;
    __stcs(ob + 0 * chan_stride, __fadd_rn(p.x, -cx));
    __stcs(ob + 1 * chan_stride, __fadd_rn(p.y, -cy));
    __stcs(ob + 2 * chan_stride, __fadd_rn(p.z, -cz));
}

// ---------------------------------------------------------------------------
// K5: feature grouping, one 128-thread block per center.
// Coalesced float4 row gather -> conflict-free smem transpose -> coalesced
// streaming stores over the sample dimension.
// ---------------------------------------------------------------------------
__global__ __launch_bounds__(128)
void group_feat_kernel(float* __restrict__ out) {
    __shared__ float4 sf4[NS][17];                  // pitch 17 float4 -> conflict-free
    __shared__ int    sidx[NS];

    const int center = blockIdx.x;
    const int b = center / SQ;
    const int s = center % SQ;
    const int tid = threadIdx.x;

    if (tid < NS) sidx[tid] = g_idx[center * NS + tid];
    __syncthreads();

    const float4* __restrict__ ft4 =
        (const float4*)(g_featT + (size_t)b * NQ * CQ);
    const int r  = tid >> 4;       // 0..7
    const int c4 = tid & 15;       // 0..15
#pragma unroll
    for (int r0 = 0; r0 < NS; r0 += 8)
        sf4[r0 + r][c4] = __ldg(ft4 + (size_t)sidx[r0 + r] * 16 + c4);
    __syncthreads();

    const int k = tid & 31;
    const int w = tid >> 5;        // 0..3
    const size_t chan_stride = (size_t)SQ * NS;
    float* ob = out + ((size_t)b * OUTC * SQ + s) * NS + k + 3 * chan_stride;
#pragma unroll
    for (int cc = w; cc < 16; cc += 4) {
        float4 v = sf4[k][cc];
        float* o = ob + (size_t)(4 * cc) * chan_stride;
        __stcs(o + 0 * chan_stride, v.x);
        __stcs(o + 1 * chan_stride, v.y);
        __stcs(o + 2 * chan_stride, v.z);
        __stcs(o + 3 * chan_stride, v.w);
    }
}

// ---------------------------------------------------------------------------
// Launch
// ---------------------------------------------------------------------------
extern "C" void kernel_launch(void* const* d_in, const int* in_sizes, int n_in,
                              void* d_out, int out_size) {
    const float* xyz     = (const float*)d_in[0];   // [B,N,3]
    const float* new_xyz = (const float*)d_in[1];   // [B,S,3]
    const float* feat    = (const float*)d_in[2];   // [B,C,N]
    float* out = (float*)d_out;                     // [B,67,S,NS]

    k1_hist<<<HB + 1024, 256>>>(xyz, feat);         // hist + tiles 0..1023
    k2_scan<<<BQ + 512, 256>>>(feat);               // scan + tiles 1024..1535
    k3_scatter<<<HB + 512, 256>>>(feat);            // scatter + tiles 1536..2047

    ball_query_grid_kernel<<<(BQ * SQ) / WARPS_B, WARPS_B * 32>>>(new_xyz, out);

    group_feat_kernel<<<BQ * SQ, 128>>>(out);
}